// round 5
// baseline (speedup 1.0000x reference)
#include <cuda_runtime.h>
#include <math.h>

#define DDIM   64
#define KCODES 2048
#define NPTS   32768       // 32 * 32 * 32
#define HW     1024        // 32 * 32
#define TMM    128         // points per block
#define TKC    32          // codes per smem tile
#define KAUG   72          // 64 + 4 aug dims + 4 zero pad (9 k-steps of 8)
#define ESTRIDE 76         // padded smem row (conflict-free B loads)
#define NITER  (KCODES / TKC)

#define C1 (1.25f * 0.00048828125f)   // 1.25 * 2^-11  (2*C1 = 1.25*2^-10)
#define C2 (1.25f * 0.000244140625f)  // 1.25 * 2^-12  (2*C2 = 1.25*2^-11)

__device__ int   g_idx[NPTS];
__device__ float g_esq[KCODES];
__device__ float g_cbt[KCODES * KAUG];   // tf32-rounded augmented codebook

__device__ __forceinline__ float to_tf32(float x) {
    float r;
    asm("cvt.rna.tf32.f32 %0, %1;" : "=f"(r) : "f"(x));
    return r;
}
__device__ __forceinline__ unsigned long long enc_key(float dist, int code) {
    unsigned int u = __float_as_uint(dist);
    u = (u & 0x80000000u) ? ~u : (u | 0x80000000u);  // total order
    return ((unsigned long long)u << 32) | (unsigned)code;
}
__device__ __forceinline__ void mma_tf32(float& c0, float& c1, float& c2, float& c3,
                                         float a0, float a1, float a2, float a3,
                                         float b0, float b1) {
    asm("mma.sync.aligned.m16n8k8.row.col.f32.tf32.tf32.f32 "
        "{%0,%1,%2,%3}, {%4,%5,%6,%7}, {%8,%9}, {%0,%1,%2,%3};"
        : "+f"(c0), "+f"(c1), "+f"(c2), "+f"(c3)
        : "r"(__float_as_uint(a0)), "r"(__float_as_uint(a1)),
          "r"(__float_as_uint(a2)), "r"(__float_as_uint(a3)),
          "r"(__float_as_uint(b0)), "r"(__float_as_uint(b1)));
}

// exact fp32 distance, same formula/order as the rel_err==0 kernels
__device__ __forceinline__ float exact_dist(const float* __restrict__ lat_b, int p_local,
                                            const float* __restrict__ cb, int code,
                                            float xsq) {
    const float* e = cb + code * DDIM;
    float s = 0.f;
    #pragma unroll 8
    for (int d = 0; d < DDIM; ++d)
        s = fmaf(__ldg(&lat_b[d * HW + p_local]), __ldg(&e[d]), s);
    return fmaf(-2.f, s, xsq) + g_esq[code];
}

// ---------------------------------------------------------------------------
// Kernel 1: prep — exact e_sq + tf32 augmented codebook rows
// ---------------------------------------------------------------------------
__global__ void prep_kernel(const float* __restrict__ cb) {
    int k = blockIdx.x * blockDim.x + threadIdx.x;
    if (k >= KCODES) return;
    const float* row = cb + (size_t)k * DDIM;
    float s = 0.f;
    #pragma unroll
    for (int d = 0; d < DDIM; ++d) { float v = row[d]; s = fmaf(v, v, s); }
    g_esq[k] = s;
    float* o = g_cbt + (size_t)k * KAUG;
    #pragma unroll
    for (int d = 0; d < DDIM; ++d) o[d] = to_tf32(row[d]);
    o[64] = to_tf32(-0.5f * s);
    o[65] = C1 * to_tf32(sqrtf(s));
    o[66] = C2 * to_tf32(s);
    o[67] = 0.f; o[68] = 0.f; o[69] = 0.f; o[70] = 0.f; o[71] = 0.f;
}

// ---------------------------------------------------------------------------
// Kernel 2: tf32 screen (pass A: T = min(dist+bnd); pass B: candidates+exact)
// 256 thr = 8 warps; warp handles 16 rows x all codes via m16n8k8 mma.
// ---------------------------------------------------------------------------
__global__ __launch_bounds__(256, 2)
void vq_screen(const float* __restrict__ laten, const float* __restrict__ cb,
               float* __restrict__ out) {
    extern __shared__ float sm[];
    float* xs   = sm;                     // [KAUG][TMM]
    float* xsqs = sm + KAUG * TMM;        // [TMM]
    float* es   = xsqs + TMM;             // [TKC][ESTRIDE]

    const int tid  = threadIdx.x;
    const int lane = tid & 31;
    const int warp = tid >> 5;
    const int g    = lane >> 2;           // 0..7
    const int q    = lane & 3;            // 0..3
    const int m0   = warp * 16;

    const int p0  = blockIdx.x * TMM;
    const int b   = p0 >> 10;
    const int hw0 = p0 & 1023;
    const float* lat_b = laten + (size_t)b * (DDIM * HW) + hw0;

    // ---- stage x: tf32 into xs, exact xsq, aug rows (threads 0..127) ----
    if (tid < TMM) {
        const int p = tid;
        float s = 0.f;
        #pragma unroll
        for (int d = 0; d < DDIM; ++d) {
            float v = lat_b[d * HW + p];
            xs[d * TMM + p] = to_tf32(v);
            s = fmaf(v, v, s);
        }
        xsqs[p] = s;
        xs[64 * TMM + p] = 1.0f;
        xs[65 * TMM + p] = to_tf32(sqrtf(s));
        xs[66 * TMM + p] = 1.0f;
        xs[67 * TMM + p] = 0.f;
        xs[68 * TMM + p] = 0.f; xs[69 * TMM + p] = 0.f;
        xs[70 * TMM + p] = 0.f; xs[71 * TMM + p] = 0.f;
    }
    __syncthreads();

    // ---- A fragments: persist across all iterations and both passes ----
    float a[9][4];
    #pragma unroll
    for (int s = 0; s < 9; ++s) {
        int k0 = s * 8;
        a[s][0] = xs[(k0 + q)     * TMM + m0 + g];
        a[s][1] = xs[(k0 + q)     * TMM + m0 + g + 8];
        a[s][2] = xs[(k0 + q + 4) * TMM + m0 + g];
        a[s][3] = xs[(k0 + q + 4) * TMM + m0 + g + 8];
    }
    const float xsq0 = xsqs[m0 + g];
    const float xsq1 = xsqs[m0 + g + 8];

    float T0 = 3.402823e+38f, T1 = 3.402823e+38f;
    unsigned long long key0 = ~0ULL, key1 = ~0ULL;

    for (int pass = 0; pass < 2; ++pass) {
        const float sgn = pass ? 1.f : -1.f;

        for (int iter = 0; iter < NITER; ++iter) {
            __syncthreads();
            {   // stage 32-code augmented tile, sign-flip bound dims
                const float* src = g_cbt + (size_t)iter * TKC * KAUG;
                #pragma unroll
                for (int j = 0; j < 9; ++j) {
                    int idx = tid * 9 + j;            // 0..2303
                    int e = idx / KAUG, d = idx - e * KAUG;
                    float v = src[idx];
                    if (d == 65 || d == 66) v *= sgn;
                    es[e * ESTRIDE + d] = v;
                }
            }
            __syncthreads();

            #pragma unroll
            for (int nt = 0; nt < 4; ++nt) {
                float c0 = 0.f, c1 = 0.f, c2 = 0.f, c3 = 0.f;
                const float* eb = es + (nt * 8 + g) * ESTRIDE;
                #pragma unroll
                for (int s = 0; s < 9; ++s) {
                    float b0 = eb[s * 8 + q];
                    float b1 = eb[s * 8 + q + 4];
                    mma_tf32(c0, c1, c2, c3, a[s][0], a[s][1], a[s][2], a[s][3], b0, b1);
                }
                if (pass == 0) {
                    // U = dist + bound
                    T0 = fminf(T0, fmaf(-2.f, c0, xsq0));
                    T0 = fminf(T0, fmaf(-2.f, c1, xsq0));
                    T1 = fminf(T1, fmaf(-2.f, c2, xsq1));
                    T1 = fminf(T1, fmaf(-2.f, c3, xsq1));
                } else {
                    // L = dist - bound; candidates get exact recheck
                    int code = iter * TKC + nt * 8 + 2 * q;
                    float L0 = fmaf(-2.f, c0, xsq0);
                    float L1 = fmaf(-2.f, c1, xsq0);
                    float L2 = fmaf(-2.f, c2, xsq1);
                    float L3 = fmaf(-2.f, c3, xsq1);
                    if (L0 <= T0) {
                        float dx = exact_dist(lat_b, m0 + g, cb, code, xsq0);
                        unsigned long long kk = enc_key(dx, code);
                        if (kk < key0) key0 = kk;
                    }
                    if (L1 <= T0) {
                        float dx = exact_dist(lat_b, m0 + g, cb, code + 1, xsq0);
                        unsigned long long kk = enc_key(dx, code + 1);
                        if (kk < key0) key0 = kk;
                    }
                    if (L2 <= T1) {
                        float dx = exact_dist(lat_b, m0 + g + 8, cb, code, xsq1);
                        unsigned long long kk = enc_key(dx, code);
                        if (kk < key1) key1 = kk;
                    }
                    if (L3 <= T1) {
                        float dx = exact_dist(lat_b, m0 + g + 8, cb, code + 1, xsq1);
                        unsigned long long kk = enc_key(dx, code + 1);
                        if (kk < key1) key1 = kk;
                    }
                }
            }
        }

        if (pass == 0) {
            // reduce T across the 4 lanes sharing each row; broadcast back
            T0 = fminf(T0, __shfl_xor_sync(0xFFFFFFFFu, T0, 1));
            T0 = fminf(T0, __shfl_xor_sync(0xFFFFFFFFu, T0, 2));
            T1 = fminf(T1, __shfl_xor_sync(0xFFFFFFFFu, T1, 1));
            T1 = fminf(T1, __shfl_xor_sync(0xFFFFFFFFu, T1, 2));
        }
    }

    // reduce keys across the 4 lanes sharing each row
    {
        unsigned long long t;
        t = __shfl_xor_sync(0xFFFFFFFFu, key0, 1); if (t < key0) key0 = t;
        t = __shfl_xor_sync(0xFFFFFFFFu, key0, 2); if (t < key0) key0 = t;
        t = __shfl_xor_sync(0xFFFFFFFFu, key1, 1); if (t < key1) key1 = t;
        t = __shfl_xor_sync(0xFFFFFFFFu, key1, 2); if (t < key1) key1 = t;
    }
    if (q == 0) {
        int pA = p0 + m0 + g;
        int pB = pA + 8;
        int cA = (int)(key0 & 0xFFFFFFFFULL);
        int cB = (int)(key1 & 0xFFFFFFFFULL);
        g_idx[pA] = cA;  out[pA] = (float)cA;
        g_idx[pB] = cB;  out[pB] = (float)cB;
    }
}

// ---------------------------------------------------------------------------
// Kernel 3: quant_laten gather (B, D, H, W), float4 writes
// ---------------------------------------------------------------------------
__global__ void gather_kernel(const float* __restrict__ cb, float* __restrict__ out) {
    int i = blockIdx.x * blockDim.x + threadIdx.x;     // over (b, d, hw/4)
    if (i < 32 * DDIM * (HW / 4)) {
        int hw4 = i & 255;
        int d   = (i >> 8) & 63;
        int b   = i >> 14;
        const int* idx = &g_idx[(b << 10) | (hw4 * 4)];
        int k0 = idx[0], k1 = idx[1], k2 = idx[2], k3 = idx[3];
        float4 v;
        v.x = __ldg(&cb[k0 * DDIM + d]);
        v.y = __ldg(&cb[k1 * DDIM + d]);
        v.z = __ldg(&cb[k2 * DDIM + d]);
        v.w = __ldg(&cb[k3 * DDIM + d]);
        *reinterpret_cast<float4*>(&out[NPTS + (size_t)i * 4]) = v;
    }
}

extern "C" void kernel_launch(void* const* d_in, const int* in_sizes, int n_in,
                              void* d_out, int out_size) {
    const float* laten = (const float*)d_in[0];   // (32, 64, 32, 32) f32
    const float* cb    = (const float*)d_in[1];   // (2048, 64) f32
    float* out = (float*)d_out;                   // [32768 idx | 2097152 quant]

    const int smem = (KAUG * TMM + TMM + TKC * ESTRIDE) * 4;   // 47,104 B
    cudaFuncSetAttribute(vq_screen, cudaFuncAttributeMaxDynamicSharedMemorySize, smem);

    prep_kernel<<<KCODES / 256, 256>>>(cb);
    vq_screen<<<NPTS / TMM, 256, smem>>>(laten, cb, out);
    gather_kernel<<<(32 * DDIM * (HW / 4)) / 256, 256>>>(cb, out);
}